// round 6
// baseline (speedup 1.0000x reference)
#include <cuda_runtime.h>

#define BB 256
#define TT 50
#define MM 20
#define EE 128
#define G3 384

typedef unsigned long long u64;

__device__ __forceinline__ void fma2(u64 &acc, u64 a, u64 b){
    asm("fma.rn.f32x2 %0, %1, %2, %0;" : "+l"(acc) : "l"(a), "l"(b));
}
__device__ __forceinline__ u64 add2(u64 a, u64 b){
    u64 r; asm("add.rn.f32x2 %0, %1, %2;" : "=l"(r) : "l"(a), "l"(b));
    return r;
}
__device__ __forceinline__ float hsum2(u64 v){
    float lo, hi;
    asm("mov.b64 {%0,%1}, %2;" : "=f"(lo), "=f"(hi) : "l"(v));
    return lo + hi;
}
__device__ __forceinline__ float sigf(float x){
    return __fdividef(1.f, 1.f + __expf(-x));
}
__device__ __forceinline__ float tanhfast(float x){
    return __fdividef(2.f, 1.f + __expf(-2.f*x)) - 1.f;
}
// opaque runtime zero, data-dependent on x (fences instruction scheduling)
__device__ __forceinline__ int zero_dep(float x){
    int r;
    asm("{\n\t.reg .b32 t;\n\tmov.b32 t, %1;\n\tand.b32 %0, t, 0;\n\t}"
        : "=r"(r) : "f"(x));
    return r;
}

// hg = dot(w_row_of_this_thread, src[0:128])   (src in shared, broadcast LDS)
__device__ __forceinline__ float dot_row(const u64* __restrict__ w,
                                         const float* __restrict__ src){
    u64 ca = 0ull, cb = 0ull;
    const ulonglong2* hp = (const ulonglong2*)src;
    #pragma unroll
    for (int k = 0; k < 32; ++k){
        ulonglong2 v = hp[k];
        fma2(ca, w[2*k  ], v.x);
        fma2(cb, w[2*k+1], v.y);
    }
    return hsum2(add2(ca, cb));
}

// ---------------------------------------------------------------------------
// Fused kernel: CTA b handles batch pair (b, 255-b).
//  Phase A: gather active ub rows into SMEM (warp-per-row).
//  Phase B: W_ih in regs; xg for all active rows -> SMEM (no per-iter barrier).
//  Phase C: W_hh in regs; 50-step GRU scan, xg/h/srz all in SMEM.
// SMEM: ub 2*50*128 + xg 2*50*384 + h 2*128 + srz 2*256 = 51968 floats = 207872 B
// ---------------------------------------------------------------------------
__global__ void __launch_bounds__(384,1) k_fused(
    const int*   __restrict__ ids,
    const int*   __restrict__ bsz,
    const int*   __restrict__ lens,
    const float* __restrict__ emb,
    const float* __restrict__ W_ih,
    const float* __restrict__ W_hh,
    const float* __restrict__ b_ih,
    const float* __restrict__ b_hh,
    const float* __restrict__ h0,
    float*       __restrict__ out)
{
    extern __shared__ float smem[];
    float* s_ub  = smem;                    // [2][TT][EE]
    float* s_xg  = smem + 2*TT*EE;          // [2][TT][G3]
    float* s_h   = s_xg + 2*TT*G3;          // [2][EE]
    float* s_srz = s_h  + 2*EE;             // [2][256]

    const int j  = threadIdx.x;
    const int b0 = blockIdx.x, b1 = (BB-1) - blockIdx.x;
    const int len0 = __ldg(lens + b0), len1 = __ldg(lens + b1);
    const int total = len0 + len1;

    // ---------------- Phase A: gather ----------------
    {
        const int wid = j >> 5, lane = j & 31;
        const float4* e4 = (const float4*)emb;
        for (int i = wid; i < total; i += 12){
            const int row = (i >= len0);
            const int t   = row ? i - len0 : i;
            const int r   = (row ? b1 : b0)*TT + t;

            const int4* ip = (const int4*)(ids + r*MM);   // 80B-aligned
            const int4 i0=__ldg(ip), i1=__ldg(ip+1), i2=__ldg(ip+2),
                       i3=__ldg(ip+3), i4=__ldg(ip+4);

            float4 v[20];
            v[0]=__ldg(e4+i0.x*32+lane);  v[1]=__ldg(e4+i0.y*32+lane);
            v[2]=__ldg(e4+i0.z*32+lane);  v[3]=__ldg(e4+i0.w*32+lane);
            v[4]=__ldg(e4+i1.x*32+lane);  v[5]=__ldg(e4+i1.y*32+lane);
            v[6]=__ldg(e4+i1.z*32+lane);  v[7]=__ldg(e4+i1.w*32+lane);
            v[8]=__ldg(e4+i2.x*32+lane);  v[9]=__ldg(e4+i2.y*32+lane);
            v[10]=__ldg(e4+i2.z*32+lane); v[11]=__ldg(e4+i2.w*32+lane);
            v[12]=__ldg(e4+i3.x*32+lane); v[13]=__ldg(e4+i3.y*32+lane);
            v[14]=__ldg(e4+i3.z*32+lane); v[15]=__ldg(e4+i3.w*32+lane);
            v[16]=__ldg(e4+i4.x*32+lane); v[17]=__ldg(e4+i4.y*32+lane);
            v[18]=__ldg(e4+i4.z*32+lane); v[19]=__ldg(e4+i4.w*32+lane);

            float4 a;
            a.x = (((v[0].x+v[1].x)+(v[2].x+v[3].x))+((v[4].x+v[5].x)+(v[6].x+v[7].x)))
                + (((v[8].x+v[9].x)+(v[10].x+v[11].x))+((v[12].x+v[13].x)+(v[14].x+v[15].x)))
                + ((v[16].x+v[17].x)+(v[18].x+v[19].x));
            a.y = (((v[0].y+v[1].y)+(v[2].y+v[3].y))+((v[4].y+v[5].y)+(v[6].y+v[7].y)))
                + (((v[8].y+v[9].y)+(v[10].y+v[11].y))+((v[12].y+v[13].y)+(v[14].y+v[15].y)))
                + ((v[16].y+v[17].y)+(v[18].y+v[19].y));
            a.z = (((v[0].z+v[1].z)+(v[2].z+v[3].z))+((v[4].z+v[5].z)+(v[6].z+v[7].z)))
                + (((v[8].z+v[9].z)+(v[10].z+v[11].z))+((v[12].z+v[13].z)+(v[14].z+v[15].z)))
                + ((v[16].z+v[17].z)+(v[18].z+v[19].z));
            a.w = (((v[0].w+v[1].w)+(v[2].w+v[3].w))+((v[4].w+v[5].w)+(v[6].w+v[7].w)))
                + (((v[8].w+v[9].w)+(v[10].w+v[11].w))+((v[12].w+v[13].w)+(v[14].w+v[15].w)))
                + ((v[16].w+v[17].w)+(v[18].w+v[19].w));

            const float inv = 1.0f / (float)__ldg(bsz + r);
            a.x *= inv; a.y *= inv; a.z *= inv; a.w *= inv;
            ((float4*)(s_ub + (row*TT + t)*EE))[lane] = a;
        }
    }
    __syncthreads();

    // keep W_ih loads after the gather phase (spill guard)
    const int dep = zero_dep(s_ub[0]);

    // ---------------- Phase B: xg ----------------
    u64 w[64];
    {
        const u64* wr = (const u64*)(W_ih + (j + dep)*EE);
        #pragma unroll
        for (int k = 0; k < 64; ++k) w[k] = __ldg(wr + k);
    }
    {
        const float bi = __ldg(b_ih + j);
        for (int i = 0; i < total; ++i){          // no per-iter barrier needed
            const int row = (i >= len0);
            const int t   = row ? i - len0 : i;
            s_xg[(row*TT + t)*G3 + j] = dot_row(w, s_ub + (row*TT + t)*EE) + bi;
        }
    }
    __syncthreads();

    // ---------------- Phase C: scan ----------------
    const int dep2 = zero_dep(s_xg[0]);
    {
        const u64* wr = (const u64*)(W_hh + (j + dep2)*EE);
        #pragma unroll
        for (int k = 0; k < 64; ++k) w[k] = __ldg(wr + k);
    }
    const float bh = __ldg(b_hh + j);

    if (j < EE){
        s_h[j]      = __ldg(h0 + b0*EE + j);
        s_h[EE + j] = __ldg(h0 + b1*EE + j);
    }
    __syncthreads();

    const int maxlen = max(len0, len1);
    for (int t = 0; t < maxlen; ++t){
        const bool a0 = (t < len0), a1 = (t < len1);
        float xg0 = 0.f, xg1 = 0.f, hg0 = 0.f, hg1 = 0.f;
        if (a0){ xg0 = s_xg[t*G3 + j];        hg0 = dot_row(w, s_h)      + bh; }
        if (a1){ xg1 = s_xg[(TT + t)*G3 + j]; hg1 = dot_row(w, s_h + EE) + bh; }

        if (j < 256){
            s_srz[j]       = hg0 + xg0;
            s_srz[256 + j] = hg1 + xg1;
        }
        __syncthreads();

        if (j >= 256){
            const int e = j - 256;
            if (a0){
                const float r  = sigf(s_srz[e]);
                const float z  = sigf(s_srz[e + 128]);
                const float n  = tanhfast(xg0 + r * hg0);     // xn + r*hn
                const float hv = (1.f - z)*n + z * s_h[e];
                s_h[e] = hv;
                out[(b0*TT + t)*EE + e] = hv;
            }
            if (a1){
                const float r  = sigf(s_srz[256 + e]);
                const float z  = sigf(s_srz[256 + e + 128]);
                const float n  = tanhfast(xg1 + r * hg1);
                const float hv = (1.f - z)*n + z * s_h[EE + e];
                s_h[EE + e] = hv;
                out[(b1*TT + t)*EE + e] = hv;
            }
        }
        __syncthreads();
    }

    // ---------------- epilogue: masked tail zeros + h_u ----------------
    {
        const float4 z4 = make_float4(0.f, 0.f, 0.f, 0.f);
        float4* p0 = (float4*)(out + (b0*TT + len0)*EE);
        const int n0 = (TT - len0) * (EE/4);
        for (int k = j; k < n0; k += 384) p0[k] = z4;
        float4* p1 = (float4*)(out + (b1*TT + len1)*EE);
        const int n1 = (TT - len1) * (EE/4);
        for (int k = j; k < n1; k += 384) p1[k] = z4;
    }
    if (j < EE){
        out[BB*TT*EE + b0*EE + j] = s_h[j];
        out[BB*TT*EE + b1*EE + j] = s_h[EE + j];
    }
}

// ---------------------------------------------------------------------------
extern "C" void kernel_launch(void* const* d_in, const int* in_sizes, int n_in,
                              void* d_out, int out_size){
    const int*   item_ids = (const int*)  d_in[0];
    const int*   bsz      = (const int*)  d_in[1];
    const int*   lengths  = (const int*)  d_in[2];
    const float* emb      = (const float*)d_in[3];
    const float* W_ih     = (const float*)d_in[4];
    const float* W_hh     = (const float*)d_in[5];
    const float* b_ih     = (const float*)d_in[6];
    const float* b_hh     = (const float*)d_in[7];
    const float* h0       = (const float*)d_in[8];
    float* out = (float*)d_out;

    const int smem_bytes = (2*TT*EE + 2*TT*G3 + 2*EE + 2*256) * 4;  // 207872
    cudaFuncSetAttribute(k_fused, cudaFuncAttributeMaxDynamicSharedMemorySize,
                         smem_bytes);
    k_fused<<<BB/2, 384, smem_bytes>>>(item_ids, bsz, lengths, emb,
                                       W_ih, W_hh, b_ih, b_hh, h0, out);
}

// round 7
// speedup vs baseline: 1.4641x; 1.4641x over previous
#include <cuda_runtime.h>

#define BB 256
#define TT 50
#define MM 20
#define EE 128
#define G3 384

typedef unsigned long long u64;

// scratch for ub only (xg now lives in SMEM)
__device__ __align__(16) float g_ub[BB*TT*EE];   // basket means (B,T,E)

__device__ __forceinline__ void fma2(u64 &acc, u64 a, u64 b){
    asm("fma.rn.f32x2 %0, %1, %2, %0;" : "+l"(acc) : "l"(a), "l"(b));
}
__device__ __forceinline__ u64 add2(u64 a, u64 b){
    u64 r; asm("add.rn.f32x2 %0, %1, %2;" : "=l"(r) : "l"(a), "l"(b));
    return r;
}
__device__ __forceinline__ float hsum2(u64 v){
    float lo, hi;
    asm("mov.b64 {%0,%1}, %2;" : "=f"(lo), "=f"(hi) : "l"(v));
    return lo + hi;
}
__device__ __forceinline__ float sigf(float x){
    return __fdividef(1.f, 1.f + __expf(-x));
}
__device__ __forceinline__ float tanhfast(float x){
    return __fdividef(2.f, 1.f + __expf(-2.f*x)) - 1.f;
}
__device__ __forceinline__ int zero_dep(float x){
    int r;
    asm("{\n\t.reg .b32 t;\n\tmov.b32 t, %1;\n\tand.b32 %0, t, 0;\n\t}"
        : "=r"(r) : "f"(x));
    return r;
}

// hg = dot(w_row_of_this_thread, src[0:128])   (src in shared, broadcast LDS)
__device__ __forceinline__ float dot_row(const u64* __restrict__ w,
                                         const float* __restrict__ src){
    u64 ca = 0ull, cb = 0ull;
    const ulonglong2* hp = (const ulonglong2*)src;
    #pragma unroll
    for (int k = 0; k < 32; ++k){
        ulonglong2 v = hp[k];
        fma2(ca, w[2*k  ], v.x);
        fma2(cb, w[2*k+1], v.y);
    }
    return hsum2(add2(ca, cb));
}

// ---------------------------------------------------------------------------
// K1: gather. One WARP per PAIR (p, 12799-p); BOTH rows' 40 emb-line loads
// issued before any reduction -> MLP ~40. launch_bounds(128,2) gives ptxas
// up to 256 regs so it keeps the loads in flight.
// ---------------------------------------------------------------------------
#define RED20(FLD) \
    ((((v[0].FLD+v[1].FLD)+(v[2].FLD+v[3].FLD))+((v[4].FLD+v[5].FLD)+(v[6].FLD+v[7].FLD))) \
    +(((v[8].FLD+v[9].FLD)+(v[10].FLD+v[11].FLD))+((v[12].FLD+v[13].FLD)+(v[14].FLD+v[15].FLD))) \
    +((v[16].FLD+v[17].FLD)+(v[18].FLD+v[19].FLD)))

__global__ void __launch_bounds__(128,2) k_gather(const int* __restrict__ ids,
                                                  const int* __restrict__ bsz,
                                                  const int* __restrict__ lens,
                                                  const float* __restrict__ emb){
    const int p    = blockIdx.x * 4 + (threadIdx.x >> 5);   // 0..6399
    const int lane = threadIdx.x & 31;
    const float4* e4 = (const float4*)emb;

    const int r0 = p, r1 = 12799 - p;
    const int b0g = r0 / TT, t0g = r0 - b0g*TT;
    const int b1g = r1 / TT, t1g = r1 - b1g*TT;
    const bool act0 = t0g < __ldg(lens + b0g);
    const bool act1 = t1g < __ldg(lens + b1g);

    float4 v[20], u[20];
    if (act0){
        const int4* ip = (const int4*)(ids + r0*MM);
        const int4 i0=__ldg(ip), i1=__ldg(ip+1), i2=__ldg(ip+2),
                   i3=__ldg(ip+3), i4=__ldg(ip+4);
        v[0]=__ldg(e4+i0.x*32+lane);  v[1]=__ldg(e4+i0.y*32+lane);
        v[2]=__ldg(e4+i0.z*32+lane);  v[3]=__ldg(e4+i0.w*32+lane);
        v[4]=__ldg(e4+i1.x*32+lane);  v[5]=__ldg(e4+i1.y*32+lane);
        v[6]=__ldg(e4+i1.z*32+lane);  v[7]=__ldg(e4+i1.w*32+lane);
        v[8]=__ldg(e4+i2.x*32+lane);  v[9]=__ldg(e4+i2.y*32+lane);
        v[10]=__ldg(e4+i2.z*32+lane); v[11]=__ldg(e4+i2.w*32+lane);
        v[12]=__ldg(e4+i3.x*32+lane); v[13]=__ldg(e4+i3.y*32+lane);
        v[14]=__ldg(e4+i3.z*32+lane); v[15]=__ldg(e4+i3.w*32+lane);
        v[16]=__ldg(e4+i4.x*32+lane); v[17]=__ldg(e4+i4.y*32+lane);
        v[18]=__ldg(e4+i4.z*32+lane); v[19]=__ldg(e4+i4.w*32+lane);
    }
    if (act1){
        const int4* ip = (const int4*)(ids + r1*MM);
        const int4 i0=__ldg(ip), i1=__ldg(ip+1), i2=__ldg(ip+2),
                   i3=__ldg(ip+3), i4=__ldg(ip+4);
        u[0]=__ldg(e4+i0.x*32+lane);  u[1]=__ldg(e4+i0.y*32+lane);
        u[2]=__ldg(e4+i0.z*32+lane);  u[3]=__ldg(e4+i0.w*32+lane);
        u[4]=__ldg(e4+i1.x*32+lane);  u[5]=__ldg(e4+i1.y*32+lane);
        u[6]=__ldg(e4+i1.z*32+lane);  u[7]=__ldg(e4+i1.w*32+lane);
        u[8]=__ldg(e4+i2.x*32+lane);  u[9]=__ldg(e4+i2.y*32+lane);
        u[10]=__ldg(e4+i2.z*32+lane); u[11]=__ldg(e4+i2.w*32+lane);
        u[12]=__ldg(e4+i3.x*32+lane); u[13]=__ldg(e4+i3.y*32+lane);
        u[14]=__ldg(e4+i3.z*32+lane); u[15]=__ldg(e4+i3.w*32+lane);
        u[16]=__ldg(e4+i4.x*32+lane); u[17]=__ldg(e4+i4.y*32+lane);
        u[18]=__ldg(e4+i4.z*32+lane); u[19]=__ldg(e4+i4.w*32+lane);
    }
    if (act0){
        const float inv = 1.0f / (float)__ldg(bsz + r0);
        float4 a;
        a.x = RED20(x)*inv; a.y = RED20(y)*inv; a.z = RED20(z)*inv; a.w = RED20(w)*inv;
        ((float4*)g_ub)[r0*32 + lane] = a;
    }
    if (act1){
        #pragma unroll
        for (int k = 0; k < 20; ++k) v[k] = u[k];
        const float inv = 1.0f / (float)__ldg(bsz + r1);
        float4 a;
        a.x = RED20(x)*inv; a.y = RED20(y)*inv; a.z = RED20(z)*inv; a.w = RED20(w)*inv;
        ((float4*)g_ub)[r1*32 + lane] = a;
    }
}

// ---------------------------------------------------------------------------
// K2: fused xg + scan. CTA b handles batch pair (b, 255-b).
//  Phase B: W_ih in regs; xg for active rows -> SMEM (columns are
//           thread-private, so no inter-phase barrier needed for s_xg).
//  Phase C: W_hh in regs; GRU scan with s_xg/s_h/s_srz in SMEM.
// SMEM: xg 2*50*384 + ub 2*2*128 + h 2*128 + srz 512 = 39424 floats = 157696 B
// ---------------------------------------------------------------------------
__global__ void __launch_bounds__(384,1) k_xgscan(
    const float* __restrict__ W_ih,
    const float* __restrict__ W_hh,
    const float* __restrict__ b_ih,
    const float* __restrict__ b_hh,
    const float* __restrict__ h0,
    const int*   __restrict__ lens,
    float*       __restrict__ out)
{
    extern __shared__ float smem[];
    float* s_xg  = smem;                    // [2][TT][G3]
    float* s_ub  = s_xg + 2*TT*G3;          // [2][2][EE]  (double buffer x pair)
    float* s_h   = s_ub + 4*EE;             // [2][EE]
    float* s_srz = s_h  + 2*EE;             // [512]

    const int j  = threadIdx.x;
    const int b0 = blockIdx.x, b1 = (BB-1) - blockIdx.x;
    const int len0 = __ldg(lens + b0), len1 = __ldg(lens + b1);
    const int maxlen = max(len0, len1);

    // ---------------- Phase B: xg -> SMEM ----------------
    u64 w[64];
    {
        const u64* wr = (const u64*)(W_ih + j*EE);
        #pragma unroll
        for (int k = 0; k < 64; ++k) w[k] = __ldg(wr + k);
    }
    const float bi = __ldg(b_ih + j);

    const int rr = j >> 5, lane = j & 31;    // loader role: warps 0-1 (j<64)
    if (j < 64){                             // preload t=0 (len >= 1 always)
        const int bb = rr ? b1 : b0;
        ((float4*)(s_ub + rr*EE))[lane] = ((const float4*)(g_ub + (bb*TT)*EE))[lane];
    }
    __syncthreads();

    for (int t = 0; t < maxlen; ++t){
        const int cur = (t & 1) * 2;         // buffer offset in rows of 128
        float4 pf; bool hav = false;
        if (j < 64){
            const int bb = rr ? b1 : b0;
            const int ln = rr ? len1 : len0;
            if (t+1 < ln){
                pf = ((const float4*)(g_ub + (bb*TT + t+1)*EE))[lane];
                hav = true;
            }
        }

        if (t < len0)
            s_xg[t*G3 + j]        = dot_row(w, s_ub + cur*EE)        + bi;
        if (t < len1)
            s_xg[(TT + t)*G3 + j] = dot_row(w, s_ub + (cur+1)*EE)    + bi;

        if (hav)
            ((float4*)(s_ub + ((cur ^ 2) + rr)*EE))[lane] = pf;
        __syncthreads();
    }

    // ---------------- Phase C: scan ----------------
    const int dep = zero_dep(s_xg[0]);       // keep W_hh load after phase B
    {
        const u64* wr = (const u64*)(W_hh + (j + dep)*EE);
        #pragma unroll
        for (int k = 0; k < 64; ++k) w[k] = __ldg(wr + k);
    }
    const float bh = __ldg(b_hh + j);

    if (j < EE){
        s_h[j]      = __ldg(h0 + b0*EE + j);
        s_h[EE + j] = __ldg(h0 + b1*EE + j);
    }
    __syncthreads();

    for (int t = 0; t < maxlen; ++t){
        const bool a0 = (t < len0), a1 = (t < len1);
        float xg0 = 0.f, xg1 = 0.f, hg0 = 0.f, hg1 = 0.f;
        if (a0){ xg0 = s_xg[t*G3 + j];        hg0 = dot_row(w, s_h)      + bh; }
        if (a1){ xg1 = s_xg[(TT + t)*G3 + j]; hg1 = dot_row(w, s_h + EE) + bh; }

        if (j < 256){
            s_srz[j]       = hg0 + xg0;
            s_srz[256 + j] = hg1 + xg1;
        }
        __syncthreads();

        if (j >= 256){
            const int e = j - 256;
            if (a0){
                const float r  = sigf(s_srz[e]);
                const float z  = sigf(s_srz[e + 128]);
                const float n  = tanhfast(xg0 + r * hg0);    // xn + r*hn
                const float hv = (1.f - z)*n + z * s_h[e];
                s_h[e] = hv;
                out[(b0*TT + t)*EE + e] = hv;
            }
            if (a1){
                const float r  = sigf(s_srz[256 + e]);
                const float z  = sigf(s_srz[384 + e]);
                const float n  = tanhfast(xg1 + r * hg1);
                const float hv = (1.f - z)*n + z * s_h[EE + e];
                s_h[EE + e] = hv;
                out[(b1*TT + t)*EE + e] = hv;
            }
        }
        __syncthreads();
    }

    // ---------------- epilogue: masked tail zeros + h_u ----------------
    {
        const float4 z4 = make_float4(0.f, 0.f, 0.f, 0.f);
        float4* p0 = (float4*)(out + (b0*TT + len0)*EE);
        const int n0 = (TT - len0) * (EE/4);
        for (int k = j; k < n0; k += 384) p0[k] = z4;
        float4* p1 = (float4*)(out + (b1*TT + len1)*EE);
        const int n1 = (TT - len1) * (EE/4);
        for (int k = j; k < n1; k += 384) p1[k] = z4;
    }
    if (j < EE){
        out[BB*TT*EE + b0*EE + j] = s_h[j];
        out[BB*TT*EE + b1*EE + j] = s_h[EE + j];
    }
}

// ---------------------------------------------------------------------------
extern "C" void kernel_launch(void* const* d_in, const int* in_sizes, int n_in,
                              void* d_out, int out_size){
    const int*   item_ids = (const int*)  d_in[0];
    const int*   bsz      = (const int*)  d_in[1];
    const int*   lengths  = (const int*)  d_in[2];
    const float* emb      = (const float*)d_in[3];
    const float* W_ih     = (const float*)d_in[4];
    const float* W_hh     = (const float*)d_in[5];
    const float* b_ih     = (const float*)d_in[6];
    const float* b_hh     = (const float*)d_in[7];
    const float* h0       = (const float*)d_in[8];
    float* out = (float*)d_out;

    const int smem_bytes = (2*TT*G3 + 4*EE + 2*EE + 512) * 4;   // 157696
    cudaFuncSetAttribute(k_xgscan, cudaFuncAttributeMaxDynamicSharedMemorySize,
                         smem_bytes);

    k_gather<<<1600, 128>>>(item_ids, bsz, lengths, emb);
    k_xgscan<<<BB/2, 384, smem_bytes>>>(W_ih, W_hh, b_ih, b_hh, h0,
                                        lengths, out);
}

// round 8
// speedup vs baseline: 1.4888x; 1.0169x over previous
#include <cuda_runtime.h>

#define BB 256
#define TT 50
#define MM 20
#define EE 128
#define G3 384

typedef unsigned long long u64;

// scratch (no cudaMalloc allowed)
__device__ __align__(16) float g_ub[BB*TT*EE];   // basket means (B,T,E)

__device__ __forceinline__ void fma2(u64 &acc, u64 a, u64 b){
    asm("fma.rn.f32x2 %0, %1, %2, %0;" : "+l"(acc) : "l"(a), "l"(b));
}
__device__ __forceinline__ float hsum2(u64 v){
    float lo, hi;
    asm("mov.b64 {%0,%1}, %2;" : "=f"(lo), "=f"(hi) : "l"(v));
    return lo + hi;
}
__device__ __forceinline__ float sigf(float x){
    return __fdividef(1.f, 1.f + __expf(-x));
}
__device__ __forceinline__ float tanhfast(float x){
    return __fdividef(2.f, 1.f + __expf(-2.f*x)) - 1.f;
}
__device__ __forceinline__ int zero_dep(float x){
    int r;
    asm("{\n\t.reg .b32 t;\n\tmov.b32 t, %1;\n\tand.b32 %0, t, 0;\n\t}"
        : "=r"(r) : "f"(x));
    return r;
}
__device__ __forceinline__ float qreduce(float f){
    f += __shfl_xor_sync(0xFFFFFFFFu, f, 1);
    f += __shfl_xor_sync(0xFFFFFFFFu, f, 2);
    return f;
}

// ---------------------------------------------------------------------------
// Split-K weight layout: thread (oq = j>>2, kq = j&3) owns rows {oq+96m},
// K-quarter [kq*32, kq*32+32). Quarter iteration order is ROTATED by 2*kq so
// the 4 quarters of a warp hit distinct banks; rotation is baked into the
// register layout at load time (all inner-loop indices compile-time).
// ---------------------------------------------------------------------------
__device__ __forceinline__ void load_w(u64 w[4][16], const float* __restrict__ W,
                                       int oq, int kq, int dep){
    #pragma unroll
    for (int m = 0; m < 4; ++m){
        const u64* wb = (const u64*)(W + (oq + 96*m + dep)*EE + kq*32);
        #pragma unroll
        for (int i = 0; i < 8; ++i){
            const int o = ((i + 2*kq) & 7) * 2;
            w[m][2*i]   = __ldg(wb + o);
            w[m][2*i+1] = __ldg(wb + o + 1);
        }
    }
}

// partial dot over this thread's quarter for 4 outputs + intra-warp reduce.
// src: shared-memory vector of 128 floats.
__device__ __forceinline__ void dot4_s(const u64 w[4][16],
                                       const float* __restrict__ src, int kq,
                                       float &f0, float &f1, float &f2, float &f3){
    u64 a0=0ull, a1=0ull, a2=0ull, a3=0ull;
    const ulonglong2* hp = (const ulonglong2*)(src + kq*32);
    #pragma unroll
    for (int i = 0; i < 8; ++i){
        const int ii = (i + 2*kq) & 7;
        ulonglong2 v = hp[ii];
        fma2(a0, w[0][2*i], v.x); fma2(a0, w[0][2*i+1], v.y);
        fma2(a1, w[1][2*i], v.x); fma2(a1, w[1][2*i+1], v.y);
        fma2(a2, w[2][2*i], v.x); fma2(a2, w[2][2*i+1], v.y);
        fma2(a3, w[3][2*i], v.x); fma2(a3, w[3][2*i+1], v.y);
    }
    f0 = qreduce(hsum2(a0)); f1 = qreduce(hsum2(a1));
    f2 = qreduce(hsum2(a2)); f3 = qreduce(hsum2(a3));
}

// same but src in global memory (phase B reads g_ub; L1-resident)
__device__ __forceinline__ void dot4_g(const u64 w[4][16],
                                       const float* __restrict__ src, int kq,
                                       float &f0, float &f1, float &f2, float &f3){
    u64 a0=0ull, a1=0ull, a2=0ull, a3=0ull;
    const ulonglong2* hp = (const ulonglong2*)(src + kq*32);
    #pragma unroll
    for (int i = 0; i < 8; ++i){
        const int ii = (i + 2*kq) & 7;
        ulonglong2 v = __ldg(hp + ii);
        fma2(a0, w[0][2*i], v.x); fma2(a0, w[0][2*i+1], v.y);
        fma2(a1, w[1][2*i], v.x); fma2(a1, w[1][2*i+1], v.y);
        fma2(a2, w[2][2*i], v.x); fma2(a2, w[2][2*i+1], v.y);
        fma2(a3, w[3][2*i], v.x); fma2(a3, w[3][2*i+1], v.y);
    }
    f0 = qreduce(hsum2(a0)); f1 = qreduce(hsum2(a1));
    f2 = qreduce(hsum2(a2)); f3 = qreduce(hsum2(a3));
}

// ---------------------------------------------------------------------------
// K1: gather (unchanged from R7 — measured ~5us)
// ---------------------------------------------------------------------------
#define RED20(FLD) \
    ((((v[0].FLD+v[1].FLD)+(v[2].FLD+v[3].FLD))+((v[4].FLD+v[5].FLD)+(v[6].FLD+v[7].FLD))) \
    +(((v[8].FLD+v[9].FLD)+(v[10].FLD+v[11].FLD))+((v[12].FLD+v[13].FLD)+(v[14].FLD+v[15].FLD))) \
    +((v[16].FLD+v[17].FLD)+(v[18].FLD+v[19].FLD)))

__global__ void __launch_bounds__(128,2) k_gather(const int* __restrict__ ids,
                                                  const int* __restrict__ bsz,
                                                  const int* __restrict__ lens,
                                                  const float* __restrict__ emb){
    const int p    = blockIdx.x * 4 + (threadIdx.x >> 5);   // 0..6399
    const int lane = threadIdx.x & 31;
    const float4* e4 = (const float4*)emb;

    const int r0 = p, r1 = 12799 - p;
    const int b0g = r0 / TT, t0g = r0 - b0g*TT;
    const int b1g = r1 / TT, t1g = r1 - b1g*TT;
    const bool act0 = t0g < __ldg(lens + b0g);
    const bool act1 = t1g < __ldg(lens + b1g);

    float4 v[20], u[20];
    if (act0){
        const int4* ip = (const int4*)(ids + r0*MM);
        const int4 i0=__ldg(ip), i1=__ldg(ip+1), i2=__ldg(ip+2),
                   i3=__ldg(ip+3), i4=__ldg(ip+4);
        v[0]=__ldg(e4+i0.x*32+lane);  v[1]=__ldg(e4+i0.y*32+lane);
        v[2]=__ldg(e4+i0.z*32+lane);  v[3]=__ldg(e4+i0.w*32+lane);
        v[4]=__ldg(e4+i1.x*32+lane);  v[5]=__ldg(e4+i1.y*32+lane);
        v[6]=__ldg(e4+i1.z*32+lane);  v[7]=__ldg(e4+i1.w*32+lane);
        v[8]=__ldg(e4+i2.x*32+lane);  v[9]=__ldg(e4+i2.y*32+lane);
        v[10]=__ldg(e4+i2.z*32+lane); v[11]=__ldg(e4+i2.w*32+lane);
        v[12]=__ldg(e4+i3.x*32+lane); v[13]=__ldg(e4+i3.y*32+lane);
        v[14]=__ldg(e4+i3.z*32+lane); v[15]=__ldg(e4+i3.w*32+lane);
        v[16]=__ldg(e4+i4.x*32+lane); v[17]=__ldg(e4+i4.y*32+lane);
        v[18]=__ldg(e4+i4.z*32+lane); v[19]=__ldg(e4+i4.w*32+lane);
    }
    if (act1){
        const int4* ip = (const int4*)(ids + r1*MM);
        const int4 i0=__ldg(ip), i1=__ldg(ip+1), i2=__ldg(ip+2),
                   i3=__ldg(ip+3), i4=__ldg(ip+4);
        u[0]=__ldg(e4+i0.x*32+lane);  u[1]=__ldg(e4+i0.y*32+lane);
        u[2]=__ldg(e4+i0.z*32+lane);  u[3]=__ldg(e4+i0.w*32+lane);
        u[4]=__ldg(e4+i1.x*32+lane);  u[5]=__ldg(e4+i1.y*32+lane);
        u[6]=__ldg(e4+i1.z*32+lane);  u[7]=__ldg(e4+i1.w*32+lane);
        u[8]=__ldg(e4+i2.x*32+lane);  u[9]=__ldg(e4+i2.y*32+lane);
        u[10]=__ldg(e4+i2.z*32+lane); u[11]=__ldg(e4+i2.w*32+lane);
        u[12]=__ldg(e4+i3.x*32+lane); u[13]=__ldg(e4+i3.y*32+lane);
        u[14]=__ldg(e4+i3.z*32+lane); u[15]=__ldg(e4+i3.w*32+lane);
        u[16]=__ldg(e4+i4.x*32+lane); u[17]=__ldg(e4+i4.y*32+lane);
        u[18]=__ldg(e4+i4.z*32+lane); u[19]=__ldg(e4+i4.w*32+lane);
    }
    if (act0){
        const float inv = 1.0f / (float)__ldg(bsz + r0);
        float4 a;
        a.x = RED20(x)*inv; a.y = RED20(y)*inv; a.z = RED20(z)*inv; a.w = RED20(w)*inv;
        ((float4*)g_ub)[r0*32 + lane] = a;
    }
    if (act1){
        #pragma unroll
        for (int k = 0; k < 20; ++k) v[k] = u[k];
        const float inv = 1.0f / (float)__ldg(bsz + r1);
        float4 a;
        a.x = RED20(x)*inv; a.y = RED20(y)*inv; a.z = RED20(z)*inv; a.w = RED20(w)*inv;
        ((float4*)g_ub)[r1*32 + lane] = a;
    }
}

// ---------------------------------------------------------------------------
// K2: fused xg + scan, split-K/4-output layout.
// SMEM: xg 2*50*384 + hg 2*384 + h 2*128 = 39424 floats = 157696 B
// ---------------------------------------------------------------------------
__global__ void __launch_bounds__(384,1) k_xgscan(
    const float* __restrict__ W_ih,
    const float* __restrict__ W_hh,
    const float* __restrict__ b_ih,
    const float* __restrict__ b_hh,
    const float* __restrict__ h0,
    const int*   __restrict__ lens,
    float*       __restrict__ out)
{
    extern __shared__ float smem[];
    float* s_xg = smem;                    // [2][TT][G3]
    float* s_hg = s_xg + 2*TT*G3;          // [2][G3]
    float* s_h  = s_hg + 2*G3;             // [2][EE]

    const int j  = threadIdx.x;
    const int oq = j >> 2, kq = j & 3;
    const int b0 = blockIdx.x, b1 = (BB-1) - blockIdx.x;
    const int len0 = __ldg(lens + b0), len1 = __ldg(lens + b1);
    const int total = len0 + len1;
    const int maxlen = max(len0, len1);

    u64 w[4][16];

    // ---------------- Phase B: xg -> SMEM (barrier-free) ----------------
    load_w(w, W_ih, oq, kq, 0);
    {
        float bi0 = __ldg(b_ih + oq),       bi1 = __ldg(b_ih + oq + 96);
        float bi2 = __ldg(b_ih + oq + 192), bi3 = __ldg(b_ih + oq + 288);
        for (int i = 0; i < total; ++i){
            const int row = (i >= len0);
            const int t   = row ? i - len0 : i;
            const float* src = g_ub + ((row ? b1 : b0)*TT + t)*EE;
            float f0, f1, f2, f3;
            dot4_g(w, src, kq, f0, f1, f2, f3);
            if (kq == 0){
                float* dst = s_xg + (row*TT + t)*G3;
                dst[oq]       = f0 + bi0;
                dst[oq + 96]  = f1 + bi1;
                dst[oq + 192] = f2 + bi2;
                dst[oq + 288] = f3 + bi3;
            }
        }
    }
    if (j < EE){
        s_h[j]      = __ldg(h0 + b0*EE + j);
        s_h[EE + j] = __ldg(h0 + b1*EE + j);
    }
    __syncthreads();

    // ---------------- Phase C: scan ----------------
    const int dep = zero_dep(s_xg[j]);
    load_w(w, W_hh, oq, kq, dep);
    const float bh0 = __ldg(b_hh + oq),       bh1 = __ldg(b_hh + oq + 96);
    const float bh2 = __ldg(b_hh + oq + 192), bh3 = __ldg(b_hh + oq + 288);

    for (int t = 0; t < maxlen; ++t){
        const bool a0 = (t < len0), a1 = (t < len1);
        if (a0){
            float f0, f1, f2, f3;
            dot4_s(w, s_h, kq, f0, f1, f2, f3);
            if (kq == 0){
                s_hg[oq]       = f0 + bh0;
                s_hg[oq + 96]  = f1 + bh1;
                s_hg[oq + 192] = f2 + bh2;
                s_hg[oq + 288] = f3 + bh3;
            }
        }
        if (a1){
            float f0, f1, f2, f3;
            dot4_s(w, s_h + EE, kq, f0, f1, f2, f3);
            if (kq == 0){
                s_hg[G3 + oq]       = f0 + bh0;
                s_hg[G3 + oq + 96]  = f1 + bh1;
                s_hg[G3 + oq + 192] = f2 + bh2;
                s_hg[G3 + oq + 288] = f3 + bh3;
            }
        }
        __syncthreads();

        if (j < 256){
            const int row = j >> 7, e = j & 127;
            const bool act = row ? a1 : a0;
            if (act){
                const float* xrow = s_xg + (row*TT + t)*G3;
                const float* hrow = s_hg + row*G3;
                const float r  = sigf(xrow[e]       + hrow[e]);
                const float z  = sigf(xrow[128 + e] + hrow[128 + e]);
                const float n  = tanhfast(xrow[256 + e] + r * hrow[256 + e]);
                const float hv = (1.f - z)*n + z * s_h[row*EE + e];
                s_h[row*EE + e] = hv;
                out[((row ? b1 : b0)*TT + t)*EE + e] = hv;
            }
        }
        __syncthreads();
    }

    // ---------------- epilogue: masked tail zeros + h_u ----------------
    {
        const float4 z4 = make_float4(0.f, 0.f, 0.f, 0.f);
        float4* p0 = (float4*)(out + (b0*TT + len0)*EE);
        const int n0 = (TT - len0) * (EE/4);
        for (int k = j; k < n0; k += 384) p0[k] = z4;
        float4* p1 = (float4*)(out + (b1*TT + len1)*EE);
        const int n1 = (TT - len1) * (EE/4);
        for (int k = j; k < n1; k += 384) p1[k] = z4;
    }
    if (j < EE){
        out[BB*TT*EE + b0*EE + j] = s_h[j];
        out[BB*TT*EE + b1*EE + j] = s_h[EE + j];
    }
}

// ---------------------------------------------------------------------------
extern "C" void kernel_launch(void* const* d_in, const int* in_sizes, int n_in,
                              void* d_out, int out_size){
    const int*   item_ids = (const int*)  d_in[0];
    const int*   bsz      = (const int*)  d_in[1];
    const int*   lengths  = (const int*)  d_in[2];
    const float* emb      = (const float*)d_in[3];
    const float* W_ih     = (const float*)d_in[4];
    const float* W_hh     = (const float*)d_in[5];
    const float* b_ih     = (const float*)d_in[6];
    const float* b_hh     = (const float*)d_in[7];
    const float* h0       = (const float*)d_in[8];
    float* out = (float*)d_out;

    const int smem_bytes = (2*TT*G3 + 2*G3 + 2*EE) * 4;   // 157696
    cudaFuncSetAttribute(k_xgscan, cudaFuncAttributeMaxDynamicSharedMemorySize,
                         smem_bytes);

    k_gather<<<1600, 128>>>(item_ids, bsz, lengths, emb);
    k_xgscan<<<BB/2, 384, smem_bytes>>>(W_ih, W_hh, b_ih, b_hh, h0,
                                        lengths, out);
}